// round 7
// baseline (speedup 1.0000x reference)
#include <cuda_runtime.h>
#include <cuda_bf16.h>

#define N_NODES   10000
#define N_EDGES   160000
#define E_TOT     170000        // edges + self loops
#define IN_DIM    128
#define HID       16
#define HEADS     50
#define HH        800           // HEADS*HID
#define OUT_DIM   10
#define N_GRAPHS  8
#define NEG_SLOPE 0.2f

// ---------------- scratch (static device globals; no allocation) ----------------
__device__ float g_xp[N_NODES * HH];        // [N, H*C] projected features (32 MB)
__device__ float g_as[N_NODES * HEADS];     // alpha_src per node/head
__device__ float g_ad[N_NODES * HEADS];     // alpha_dst per node/head
__device__ float g_denom[N_NODES * HEADS];  // softmax denominators
__device__ float g_h[N_NODES * HID];        // head-mean aggregated features
__device__ float g_gsum[N_GRAPHS * HID];
__device__ float g_cnt[N_GRAPHS];

__device__ int g_src[E_TOT];                // canonical int32 edge sources (+self loops)
__device__ int g_dst[E_TOT];                // canonical int32 edge targets (+self loops)
__device__ int g_batch[N_NODES];            // canonical int32 batch ids
__device__ int g_is64_ei;                   // 1 if edge_index stored as int64
__device__ int g_is64_b;                    // 1 if batch stored as int64

// ---------------- K-1: detect index dtype (int32 vs int64 storage) ----------
// int64 little-endian values < 2^31 have zero hi-words at odd int32 positions;
// int32 storage has node-ids / graph-ids there. Sample 64 spread positions.
__global__ void detect_kernel(const int* __restrict__ ei32,
                              const int* __restrict__ b32) {
    if (threadIdx.x == 0) {
        int all0 = 1;
        for (int k = 0; k < 64; k++) {
            int e = (k * 2499 + 7) % N_EDGES;       // spread over first row
            if (ei32[2 * e + 1] != 0) { all0 = 0; break; }
        }
        g_is64_ei = all0;
        all0 = 1;
        for (int k = 0; k < 64; k++) {
            int j = 5001 + 2 * k;                   // odd words, mid-array
            if (b32[j] != 0) { all0 = 0; break; }   // int32: batch[j] ~ graph 4
        }
        g_is64_b = all0;
    }
}

// ---------------- K0a: canonicalize indices (+ append self loops) ------------
__global__ void build_idx_kernel(const void* __restrict__ ei,
                                 const void* __restrict__ batch) {
    int e = blockIdx.x * blockDim.x + threadIdx.x;
    if (e < E_TOT) {
        int s, d;
        if (e < N_EDGES) {
            if (g_is64_ei) {
                const long long* p = (const long long*)ei;
                s = (int)p[e]; d = (int)p[N_EDGES + e];
            } else {
                const int* p = (const int*)ei;
                s = p[e]; d = p[N_EDGES + e];
            }
            // defensive clamp: wrong-answer beats sticky crash
            s = min(max(s, 0), N_NODES - 1);
            d = min(max(d, 0), N_NODES - 1);
        } else {
            s = d = e - N_EDGES;
        }
        g_src[e] = s;
        g_dst[e] = d;
    }
    if (e < N_NODES) {
        int b = g_is64_b ? (int)((const long long*)batch)[e]
                         : ((const int*)batch)[e];
        g_batch[e] = min(max(b, 0), N_GRAPHS - 1);
    }
}

// ---------------- K0b: zero the accumulators ----------------
__global__ void init_kernel() {
    int i = blockIdx.x * blockDim.x + threadIdx.x;
    if (i < N_NODES * HEADS) g_denom[i] = 0.f;
    if (i < N_NODES * HID)   g_h[i] = 0.f;
    if (i < N_GRAPHS * HID)  g_gsum[i] = 0.f;
    if (i < N_GRAPHS)        g_cnt[i] = 0.f;
}

// ---------------- K1: xp = x @ W   (10000x128 @ 128x800) ----------------
// 64x64 tile, 256 threads, 4x4 per-thread register tile, K tiled by 16.
__global__ void gemm_xp(const float* __restrict__ X, const float* __restrict__ W) {
    __shared__ float As[64][17];   // padded vs bank conflicts
    __shared__ float Bs[16][64];

    const int tid = threadIdx.x;
    const int tx = tid & 15;        // 0..15 -> output col group
    const int ty = tid >> 4;        // 0..15 -> output row group
    const int rowBase = blockIdx.y * 64;
    const int colBase = blockIdx.x * 64;

    float acc[4][4];
#pragma unroll
    for (int i = 0; i < 4; i++)
#pragma unroll
        for (int j = 0; j < 4; j++) acc[i][j] = 0.f;

    for (int kk = 0; kk < IN_DIM; kk += 16) {
        // load A tile 64x16 (each thread: one float4)
        {
            int r = tid >> 2;            // 0..63
            int c = (tid & 3) * 4;       // 0,4,8,12
            int grow = rowBase + r;
            if (grow < N_NODES) {
                float4 v = *(const float4*)&X[grow * IN_DIM + kk + c];
                As[r][c] = v.x; As[r][c + 1] = v.y; As[r][c + 2] = v.z; As[r][c + 3] = v.w;
            } else {
                As[r][c] = 0.f; As[r][c + 1] = 0.f; As[r][c + 2] = 0.f; As[r][c + 3] = 0.f;
            }
        }
        // load B tile 16x64 (each thread: 4 guarded scalars)
        {
            int r = tid >> 4;            // 0..15
            int c = (tid & 15) * 4;      // 0..60
            const float* Wp = &W[(kk + r) * HH];
#pragma unroll
            for (int j = 0; j < 4; j++) {
                int gcol = colBase + c + j;
                Bs[r][c + j] = (gcol < HH) ? Wp[gcol] : 0.f;
            }
        }
        __syncthreads();

#pragma unroll
        for (int k = 0; k < 16; k++) {
            float a0 = As[ty * 4 + 0][k];
            float a1 = As[ty * 4 + 1][k];
            float a2 = As[ty * 4 + 2][k];
            float a3 = As[ty * 4 + 3][k];
            float4 b = *(const float4*)&Bs[k][tx * 4];
            acc[0][0] += a0 * b.x; acc[0][1] += a0 * b.y; acc[0][2] += a0 * b.z; acc[0][3] += a0 * b.w;
            acc[1][0] += a1 * b.x; acc[1][1] += a1 * b.y; acc[1][2] += a1 * b.z; acc[1][3] += a1 * b.w;
            acc[2][0] += a2 * b.x; acc[2][1] += a2 * b.y; acc[2][2] += a2 * b.z; acc[2][3] += a2 * b.w;
            acc[3][0] += a3 * b.x; acc[3][1] += a3 * b.y; acc[3][2] += a3 * b.z; acc[3][3] += a3 * b.w;
        }
        __syncthreads();
    }

#pragma unroll
    for (int i = 0; i < 4; i++) {
        int gr = rowBase + ty * 4 + i;
        if (gr >= N_NODES) continue;
#pragma unroll
        for (int j = 0; j < 4; j++) {
            int gc = colBase + tx * 4 + j;
            if (gc < HH) g_xp[gr * HH + gc] = acc[i][j];
        }
    }
}

// ---------------- K2: per-node attention coefficients ----------------
// alpha_s[n,h] = xp[n,h,:] . a_src[h,:]   (and same for dst)
__global__ void alpha_kernel(const float* __restrict__ a_src, const float* __restrict__ a_dst) {
    int idx = blockIdx.x * blockDim.x + threadIdx.x;
    if (idx >= N_NODES * HEADS) return;
    int n = idx / HEADS;
    int h = idx - n * HEADS;
    const float* xp = &g_xp[n * HH + h * HID];
    const float* as = &a_src[h * HID];
    const float* ad = &a_dst[h * HID];
    float s = 0.f, d = 0.f;
#pragma unroll
    for (int c = 0; c < HID; c++) {
        float v = xp[c];
        s += v * __ldg(&as[c]);
        d += v * __ldg(&ad[c]);
    }
    g_as[idx] = s;
    g_ad[idx] = d;
}

// ---------------- K3: softmax denominators (edge pass 1) ----------------
// One thread per (edge, head).
__global__ void denom_kernel() {
    int idx = blockIdx.x * blockDim.x + threadIdx.x;
    if (idx >= E_TOT * HEADS) return;
    int e = idx / HEADS;
    int h = idx - e * HEADS;
    int src = g_src[e];
    int dst = g_dst[e];
    float l = g_as[src * HEADS + h] + g_ad[dst * HEADS + h];
    l = (l > 0.f) ? l : NEG_SLOPE * l;
    atomicAdd(&g_denom[dst * HEADS + h], __expf(l));
}

// ---------------- K4: weighted aggregate with fused head-mean (edge pass 2) ---
// One warp per edge. Contribution to h[dst,c] = (1/H) * sum_h alpha_eh * xp[src,h,c]
// => only 16 atomics per edge instead of 800.
__global__ void agg_kernel() {
    __shared__ float ws[8][HEADS];
    const int warp = threadIdx.x >> 5;
    const int lane = threadIdx.x & 31;
    const int e = blockIdx.x * 8 + warp;
    if (e >= E_TOT) return;

    const int src = g_src[e];
    const int dst = g_dst[e];

    for (int h = lane; h < HEADS; h += 32) {
        float l = g_as[src * HEADS + h] + g_ad[dst * HEADS + h];
        l = (l > 0.f) ? l : NEG_SLOPE * l;
        ws[warp][h] = __expf(l) / g_denom[dst * HEADS + h];
    }
    __syncwarp();

    const int c = lane & 15;
    const int half = lane >> 4;             // 0: heads 0..24, 1: heads 25..49
    const float* xp = &g_xp[src * HH];
    float acc = 0.f;
#pragma unroll 5
    for (int h = half * 25; h < half * 25 + 25; h++)
        acc += ws[warp][h] * xp[h * HID + c];
    acc += __shfl_down_sync(0xffffffffu, acc, 16);
    if (lane < 16)
        atomicAdd(&g_h[dst * HID + c], acc * (1.f / HEADS));
}

// ---------------- K5: global mean pool accumulation ----------------
__global__ void pool_kernel() {
    int idx = blockIdx.x * blockDim.x + threadIdx.x;
    if (idx >= N_NODES * HID) return;
    int n = idx / HID;
    int c = idx - n * HID;
    int g = g_batch[n];
    atomicAdd(&g_gsum[g * HID + c], g_h[idx]);
    if (c == 0) atomicAdd(&g_cnt[g], 1.f);
}

// ---------------- K6: pooled / cnt + bias, then FC ----------------
__global__ void final_kernel(const float* __restrict__ bias,
                             const float* __restrict__ fcw,
                             const float* __restrict__ fcb,
                             float* __restrict__ out) {
    int t = threadIdx.x;
    if (t >= N_GRAPHS * OUT_DIM) return;
    int g = t / OUT_DIM;
    int o = t - g * OUT_DIM;
    float cnt = fmaxf(g_cnt[g], 1.f);
    float acc = fcb[o];
#pragma unroll
    for (int c = 0; c < HID; c++)
        acc += (g_gsum[g * HID + c] / cnt + bias[c]) * fcw[c * OUT_DIM + o];
    out[t] = acc;
}

// ---------------- launch ----------------
// Identify inputs by element count (fallback: byte count). Expected element
// counts: x=1,280,000  edge_index=320,000  batch=10,000  W=102,400
//         a_src=800 (1st)  a_dst=800 (2nd)  bias=16  fc_w=160  fc_b=10
//         num_graphs=1 (ignored)
extern "C" void kernel_launch(void* const* d_in, const int* in_sizes, int n_in,
                              void* d_out, int out_size) {
    const float* x = 0;  const void* ei = 0;  const void* batch = 0;
    const float* W = 0;  const float* a_src = 0; const float* a_dst = 0;
    const float* bias = 0; const float* fcw = 0; const float* fcb = 0;

    for (int pass = 0; pass < 2 && !x; pass++) {
        // pass 0: element counts; pass 1: byte counts (float=4B, idx=8B int64)
        a_src = 0; a_dst = 0;
        for (int i = 0; i < n_in; i++) {
            long long sz = in_sizes[i];
            if (pass == 1) {
                // convert byte count back to elements (4B floats, 8B int64 idx)
                if (sz == 2LL * N_EDGES * 8) sz = 2 * N_EDGES;
                else if (sz == (long long)N_NODES * 8) sz = N_NODES;
                else sz /= 4;
            }
            const void* p = d_in[i];
            switch (sz) {
                case (long long)N_NODES * IN_DIM: x = (const float*)p; break;
                case 2LL * N_EDGES:       ei = p; break;
                case (long long)N_NODES:  batch = p; break;
                case (long long)IN_DIM * HH: W = (const float*)p; break;
                case (long long)HEADS * HID:
                    if (!a_src) a_src = (const float*)p; else a_dst = (const float*)p;
                    break;
                case HID:             bias = (const float*)p; break;
                case HID * OUT_DIM:   fcw = (const float*)p; break;
                case OUT_DIM:         fcb = (const float*)p; break;
                default: break;   // num_graphs scalar or unknown -> ignore
            }
        }
    }
    float* out = (float*)d_out;

    detect_kernel<<<1, 32>>>((const int*)ei, (const int*)batch);
    build_idx_kernel<<<(E_TOT + 255) / 256, 256>>>(ei, batch);
    {
        int n = N_NODES * HEADS;   // largest buffer to zero
        init_kernel<<<(n + 255) / 256, 256>>>();
    }
    {
        dim3 grid((HH + 63) / 64, (N_NODES + 63) / 64);
        gemm_xp<<<grid, 256>>>(x, W);
    }
    {
        int n = N_NODES * HEADS;
        alpha_kernel<<<(n + 255) / 256, 256>>>(a_src, a_dst);
    }
    {
        int n = E_TOT * HEADS;
        denom_kernel<<<(n + 255) / 256, 256>>>();
    }
    {
        int blocks = (E_TOT + 7) / 8;   // 8 warps (edges) per block
        agg_kernel<<<blocks, 256>>>();
    }
    {
        int n = N_NODES * HID;
        pool_kernel<<<(n + 255) / 256, 256>>>();
    }
    final_kernel<<<1, 128>>>(bias, fcw, fcb, out);
}

// round 9
// speedup vs baseline: 1.2694x; 1.2694x over previous
#include <cuda_runtime.h>
#include <cuda_bf16.h>

#define N_NODES   10000
#define N_EDGES   160000
#define E_TOT     170000        // edges + self loops
#define IN_DIM    128
#define HID       16
#define HEADS     50
#define HH        800           // HEADS*HID
#define OUT_DIM   10
#define N_GRAPHS  8
#define NEG_SLOPE 0.2f

// ---------------- scratch (static device globals; no allocation) ----------------
__device__ float g_xp[N_NODES * HH];        // [N, H*C] projected features (32 MB)
__device__ float g_as[N_NODES * HEADS];     // alpha_src per node/head
__device__ float g_ad[N_NODES * HEADS];     // alpha_dst per node/head
__device__ float g_gsum[N_GRAPHS * HID];
__device__ float g_cnt[N_GRAPHS];

__device__ int g_src[E_TOT];                // canonical int32 edge sources (+self loops)
__device__ int g_dst[E_TOT];                // canonical int32 edge targets (+self loops)
__device__ int g_batch[N_NODES];            // canonical int32 batch ids
__device__ int g_deg[N_NODES];              // in-degree per dst
__device__ int g_off[N_NODES + 1];          // CSR offsets
__device__ int g_pos[N_NODES];              // scatter cursors
__device__ int g_csr_src[E_TOT];            // CSR: sources grouped by dst
__device__ int g_is64_ei;                   // 1 if edge_index stored as int64
__device__ int g_is64_b;                    // 1 if batch stored as int64

// ---------------- K-1: detect index dtype (int32 vs int64 storage) ----------
__global__ void detect_kernel(const int* __restrict__ ei32,
                              const int* __restrict__ b32) {
    if (threadIdx.x == 0) {
        int all0 = 1;
        for (int k = 0; k < 64; k++) {
            int e = (k * 2499 + 7) % N_EDGES;
            if (ei32[2 * e + 1] != 0) { all0 = 0; break; }
        }
        g_is64_ei = all0;
        all0 = 1;
        for (int k = 0; k < 64; k++) {
            int j = 5001 + 2 * k;
            if (b32[j] != 0) { all0 = 0; break; }
        }
        g_is64_b = all0;
    }
}

// ---------------- K0: zero accumulators / counters ----------------
__global__ void init_kernel() {
    int i = blockIdx.x * blockDim.x + threadIdx.x;
    if (i < N_NODES) { g_deg[i] = 0; g_pos[i] = 0; }
    if (i < N_GRAPHS * HID) g_gsum[i] = 0.f;
    if (i < N_GRAPHS)       g_cnt[i] = 0.f;
}

// ---------------- K0a: canonicalize indices, append self loops, count degrees --
__global__ void build_idx_kernel(const void* __restrict__ ei,
                                 const void* __restrict__ batch) {
    int e = blockIdx.x * blockDim.x + threadIdx.x;
    if (e < E_TOT) {
        int s, d;
        if (e < N_EDGES) {
            if (g_is64_ei) {
                const long long* p = (const long long*)ei;
                s = (int)p[e]; d = (int)p[N_EDGES + e];
            } else {
                const int* p = (const int*)ei;
                s = p[e]; d = p[N_EDGES + e];
            }
            s = min(max(s, 0), N_NODES - 1);
            d = min(max(d, 0), N_NODES - 1);
        } else {
            s = d = e - N_EDGES;
        }
        g_src[e] = s;
        g_dst[e] = d;
        atomicAdd(&g_deg[d], 1);
    }
    if (e < N_NODES) {
        int b = g_is64_b ? (int)((const long long*)batch)[e]
                         : ((const int*)batch)[e];
        g_batch[e] = min(max(b, 0), N_GRAPHS - 1);
    }
}

// ---------------- K0b: exclusive scan of degrees -> CSR offsets (1 block) ----
__global__ void scan_kernel() {
    __shared__ int part[1024];
    const int PER = 10;                         // 1024*10 >= N_NODES
    int tid = threadIdx.x;
    int base = tid * PER;
    int loc[PER];
    int s = 0;
    for (int i = 0; i < PER; i++) {
        int idx = base + i;
        int v = (idx < N_NODES) ? g_deg[idx] : 0;
        loc[i] = s;
        s += v;
    }
    part[tid] = s;
    __syncthreads();
    for (int off = 1; off < 1024; off <<= 1) {
        int v = (tid >= off) ? part[tid - off] : 0;
        __syncthreads();
        part[tid] += v;
        __syncthreads();
    }
    int blockExcl = part[tid] - s;
    for (int i = 0; i < PER; i++) {
        int idx = base + i;
        if (idx < N_NODES) g_off[idx] = blockExcl + loc[i];
    }
    if (tid == 1023) g_off[N_NODES] = part[1023];
}

// ---------------- K0c: scatter edges into CSR ----------------
__global__ void scatter_kernel() {
    int e = blockIdx.x * blockDim.x + threadIdx.x;
    if (e >= E_TOT) return;
    int d = g_dst[e];
    int p = atomicAdd(&g_pos[d], 1);
    g_csr_src[g_off[d] + p] = g_src[e];
}

// ---------------- K1: xp = x @ W   (10000x128 @ 128x800) ----------------
// 128x128 tile, 256 threads, 8x8 per-thread microtile, K tiled by 16.
// As stored K-major-transposed for conflict-light float4 fragment loads.
__global__ __launch_bounds__(256) void gemm_xp(const float* __restrict__ X,
                                               const float* __restrict__ W) {
    __shared__ float As[16][128];
    __shared__ float Bs[16][128];

    const int tid = threadIdx.x;
    const int tx = tid & 15;         // col group (8 cols)
    const int ty = tid >> 4;         // row group (8 rows)
    const int rowBase = blockIdx.y * 128;
    const int colBase = blockIdx.x * 128;

    float acc[8][8];
#pragma unroll
    for (int i = 0; i < 8; i++)
#pragma unroll
        for (int j = 0; j < 8; j++) acc[i][j] = 0.f;

    for (int kk = 0; kk < IN_DIM; kk += 16) {
        // load A tile 128x16 (512 float4 slots, 2 per thread), store transposed
#pragma unroll
        for (int i = 0; i < 2; i++) {
            int s = tid * 2 + i;
            int r = s >> 2;               // 0..127
            int kq = (s & 3) * 4;         // 0,4,8,12
            int grow = rowBase + r;
            float4 v = make_float4(0.f, 0.f, 0.f, 0.f);
            if (grow < N_NODES)
                v = *(const float4*)&X[grow * IN_DIM + kk + kq];
            As[kq + 0][r] = v.x; As[kq + 1][r] = v.y;
            As[kq + 2][r] = v.z; As[kq + 3][r] = v.w;
        }
        // load B tile 16x128 (512 float4 slots, 2 per thread)
#pragma unroll
        for (int i = 0; i < 2; i++) {
            int s = tid * 2 + i;
            int r = s >> 5;               // 0..15
            int cq = (s & 31) * 4;        // 0..124
            int gcol = colBase + cq;      // multiple of 4; HH=800 multiple of 4
            float4 v = make_float4(0.f, 0.f, 0.f, 0.f);
            if (gcol < HH)
                v = *(const float4*)&W[(kk + r) * HH + gcol];
            *(float4*)&Bs[r][cq] = v;
        }
        __syncthreads();

#pragma unroll
        for (int k = 0; k < 16; k++) {
            float a[8], b[8];
            *(float4*)&a[0] = *(const float4*)&As[k][ty * 8];
            *(float4*)&a[4] = *(const float4*)&As[k][ty * 8 + 4];
            *(float4*)&b[0] = *(const float4*)&Bs[k][tx * 8];
            *(float4*)&b[4] = *(const float4*)&Bs[k][tx * 8 + 4];
#pragma unroll
            for (int i = 0; i < 8; i++)
#pragma unroll
                for (int j = 0; j < 8; j++)
                    acc[i][j] += a[i] * b[j];
        }
        __syncthreads();
    }

#pragma unroll
    for (int i = 0; i < 8; i++) {
        int gr = rowBase + ty * 8 + i;
        if (gr >= N_NODES) continue;
#pragma unroll
        for (int j4 = 0; j4 < 8; j4 += 4) {
            int gc = colBase + tx * 8 + j4;     // multiple of 4
            if (gc < HH)
                *(float4*)&g_xp[(size_t)gr * HH + gc] =
                    make_float4(acc[i][j4], acc[i][j4 + 1], acc[i][j4 + 2], acc[i][j4 + 3]);
        }
    }
}

// ---------------- K2: per-node attention coefficients ----------------
__global__ void alpha_kernel(const float* __restrict__ a_src,
                             const float* __restrict__ a_dst) {
    int idx = blockIdx.x * blockDim.x + threadIdx.x;
    if (idx >= N_NODES * HEADS) return;
    int n = idx / HEADS;
    int h = idx - n * HEADS;
    const float4* xp = (const float4*)&g_xp[(size_t)n * HH + h * HID];
    const float4* as = (const float4*)&a_src[h * HID];
    const float4* ad = (const float4*)&a_dst[h * HID];
    float s = 0.f, d = 0.f;
#pragma unroll
    for (int c4 = 0; c4 < 4; c4++) {
        float4 v = xp[c4];
        float4 sa = __ldg(&as[c4]);
        float4 da = __ldg(&ad[c4]);
        s += v.x * sa.x + v.y * sa.y + v.z * sa.z + v.w * sa.w;
        d += v.x * da.x + v.y * da.y + v.z * da.z + v.w * da.w;
    }
    g_as[idx] = s;
    g_ad[idx] = d;
}

// ---------------- K4: fused softmax-denominator + weighted aggregate + pool ---
// One warp per destination node. Pass 1: per-head denominators in registers.
// Pass 2: alpha-weighted, head-mean-fused aggregation; epilogue adds straight
// into the graph pooling sums. No global atomics except the 128-address pool.
__global__ __launch_bounds__(256) void agg_csr() {
    __shared__ float inv[8][HEADS];
    __shared__ float ws[8][HEADS];
    const int warp = threadIdx.x >> 5;
    const int lane = threadIdx.x & 31;
    const int n = blockIdx.x * 8 + warp;
    if (n >= N_NODES) return;

    const int beg = g_off[n];
    const int end = g_off[n + 1];

    // dst attention components for this node (heads lane and lane+32)
    const float ad0 = g_ad[n * HEADS + lane];
    const float ad1 = (lane < HEADS - 32) ? g_ad[n * HEADS + 32 + lane] : 0.f;

    // ---- pass 1: denominators ----
    float d0 = 0.f, d1 = 0.f;
    for (int e = beg; e < end; e++) {
        int src = g_csr_src[e];
        const float* as = &g_as[src * HEADS];
        float l0 = as[lane] + ad0;
        l0 = (l0 > 0.f) ? l0 : NEG_SLOPE * l0;
        d0 += __expf(l0);
        if (lane < HEADS - 32) {
            float l1 = as[32 + lane] + ad1;
            l1 = (l1 > 0.f) ? l1 : NEG_SLOPE * l1;
            d1 += __expf(l1);
        }
    }
    inv[warp][lane] = 1.f / d0;
    if (lane < HEADS - 32) inv[warp][32 + lane] = 1.f / d1;
    __syncwarp();

    // ---- pass 2: weighted aggregation with fused head-mean ----
    const int c = lane & 15;
    const int half = lane >> 4;
    float acc = 0.f;
    for (int e = beg; e < end; e++) {
        int src = g_csr_src[e];
        const float* as = &g_as[src * HEADS];
        float l0 = as[lane] + ad0;
        l0 = (l0 > 0.f) ? l0 : NEG_SLOPE * l0;
        ws[warp][lane] = __expf(l0) * inv[warp][lane];
        if (lane < HEADS - 32) {
            float l1 = as[32 + lane] + ad1;
            l1 = (l1 > 0.f) ? l1 : NEG_SLOPE * l1;
            ws[warp][32 + lane] = __expf(l1) * inv[warp][32 + lane];
        }
        __syncwarp();
        const float* xp = &g_xp[(size_t)src * HH];
#pragma unroll 5
        for (int h = half * 25; h < half * 25 + 25; h++)
            acc += ws[warp][h] * xp[h * HID + c];
        __syncwarp();
    }
    acc += __shfl_down_sync(0xffffffffu, acc, 16);
    if (lane < 16) {
        float val = acc * (1.f / HEADS);       // h[n, c] (bias added in final)
        int b = g_batch[n];
        atomicAdd(&g_gsum[b * HID + c], val);
        if (lane == 0) atomicAdd(&g_cnt[b], 1.f);
    }
}

// ---------------- K6: pooled / cnt + bias, then FC ----------------
__global__ void final_kernel(const float* __restrict__ bias,
                             const float* __restrict__ fcw,
                             const float* __restrict__ fcb,
                             float* __restrict__ out) {
    int t = threadIdx.x;
    if (t >= N_GRAPHS * OUT_DIM) return;
    int g = t / OUT_DIM;
    int o = t - g * OUT_DIM;
    float cnt = fmaxf(g_cnt[g], 1.f);
    float acc = fcb[o];
#pragma unroll
    for (int c = 0; c < HID; c++)
        acc += (g_gsum[g * HID + c] / cnt + bias[c]) * fcw[c * OUT_DIM + o];
    out[t] = acc;
}

// ---------------- launch ----------------
extern "C" void kernel_launch(void* const* d_in, const int* in_sizes, int n_in,
                              void* d_out, int out_size) {
    const float* x = 0;  const void* ei = 0;  const void* batch = 0;
    const float* W = 0;  const float* a_src = 0; const float* a_dst = 0;
    const float* bias = 0; const float* fcw = 0; const float* fcb = 0;

    for (int pass = 0; pass < 2 && !x; pass++) {
        a_src = 0; a_dst = 0;
        for (int i = 0; i < n_in; i++) {
            long long sz = in_sizes[i];
            if (pass == 1) {
                if (sz == 2LL * N_EDGES * 8) sz = 2 * N_EDGES;
                else if (sz == (long long)N_NODES * 8) sz = N_NODES;
                else sz /= 4;
            }
            const void* p = d_in[i];
            switch (sz) {
                case (long long)N_NODES * IN_DIM: x = (const float*)p; break;
                case 2LL * N_EDGES:       ei = p; break;
                case (long long)N_NODES:  batch = p; break;
                case (long long)IN_DIM * HH: W = (const float*)p; break;
                case (long long)HEADS * HID:
                    if (!a_src) a_src = (const float*)p; else a_dst = (const float*)p;
                    break;
                case HID:             bias = (const float*)p; break;
                case HID * OUT_DIM:   fcw = (const float*)p; break;
                case OUT_DIM:         fcb = (const float*)p; break;
                default: break;
            }
        }
    }
    float* out = (float*)d_out;

    detect_kernel<<<1, 32>>>((const int*)ei, (const int*)batch);
    init_kernel<<<(N_NODES + 255) / 256, 256>>>();
    build_idx_kernel<<<(E_TOT + 255) / 256, 256>>>(ei, batch);
    scan_kernel<<<1, 1024>>>();
    scatter_kernel<<<(E_TOT + 255) / 256, 256>>>();
    {
        dim3 grid((HH + 127) / 128, (N_NODES + 127) / 128);
        gemm_xp<<<grid, 256>>>(x, W);
    }
    {
        int n = N_NODES * HEADS;
        alpha_kernel<<<(n + 255) / 256, 256>>>(a_src, a_dst);
    }
    agg_csr<<<(N_NODES + 7) / 8, 256>>>();
    final_kernel<<<1, 128>>>(bias, fcw, fcb, out);
}